// round 11
// baseline (speedup 1.0000x reference)
#include <cuda_runtime.h>
#include <cstdint>

#define NN 40000
#define EE 640000

// ---------------- device scratch ----------------
__device__ __align__(16) float g_h[(size_t)NN * 160];
__device__ __align__(16) float g_agg[(size_t)NN * 480];
__device__ int g_cnt[NN];
__device__ int g_off[NN];
__device__ int g_perm[EE];

static constexpr float INV8        = 0.125f;
static constexpr float INV_SQRT32  = 0.17677669529663687f;
static constexpr float INV_SQRT3   = 0.57735026918962576f;
static constexpr float INV_SQRT2   = 0.70710678118654752f;
static constexpr float INV_SQRT96  = 0.10206207261596575f;
static constexpr float INV_SQRT128 = 0.08838834764831845f;
static constexpr float INV_NN      = 0.25f;

__device__ __forceinline__ float sigmoidf_(float x) { return 1.f / (1.f + __expf(-x)); }
__device__ __forceinline__ float siluf_(float x)    { return x / (1.f + __expf(-x)); }

#define GBAR(id) asm volatile("bar.sync %0, 512;" :: "r"(id) : "memory")

// ---------------- sort + zero kernels ----------------
__global__ void zero_all_kernel() {
    size_t i = (size_t)blockIdx.x * blockDim.x + threadIdx.x;
    if (i < (size_t)NN * 120) reinterpret_cast<float4*>(g_agg)[i] = make_float4(0.f, 0.f, 0.f, 0.f);
    if (i < NN) g_cnt[i] = 0;
}
__global__ void hist_kernel(const int* __restrict__ edst) {
    int e = blockIdx.x * blockDim.x + threadIdx.x;
    if (e < EE) atomicAdd(&g_cnt[edst[e]], 1);
}
__global__ void scan_kernel() {
    __shared__ int wtot[32];
    __shared__ int carry;
    int t = threadIdx.x, lane = t & 31, w = t >> 5;
    if (t == 0) carry = 0;
    __syncthreads();
    for (int b = 0; b < NN; b += 1024) {
        int i = b + t;
        int v = (i < NN) ? g_cnt[i] : 0;
        int inc = v;
        #pragma unroll
        for (int d = 1; d < 32; d <<= 1) {
            int u = __shfl_up_sync(0xffffffffu, inc, d);
            if (lane >= d) inc += u;
        }
        if (lane == 31) wtot[w] = inc;
        __syncthreads();
        if (w == 0) {
            int s = wtot[lane];
            #pragma unroll
            for (int d = 1; d < 32; d <<= 1) {
                int u = __shfl_up_sync(0xffffffffu, s, d);
                if (lane >= d) s += u;
            }
            wtot[lane] = s;
        }
        __syncthreads();
        int wpref = (w == 0) ? 0 : wtot[w - 1];
        if (i < NN) g_off[i] = carry + wpref + inc - v;
        __syncthreads();
        if (t == 0) carry += wtot[31];
        __syncthreads();
    }
}
__global__ void scatter_kernel(const int* __restrict__ edst) {
    int e = blockIdx.x * blockDim.x + threadIdx.x;
    if (e < EE) {
        int p = atomicAdd(&g_off[edst[e]], 1);
        g_perm[p] = e;
    }
}

// ---------------- node pre ----------------
__global__ void __launch_bounds__(640) node_pre_kernel(
    const float* __restrict__ nf, const float* __restrict__ na,
    const float* __restrict__ lin1_ws, const float* __restrict__ lin1_wv)
{
    __shared__ float ws[64 * 64];
    __shared__ float wv[32 * 32];
    __shared__ float sv[32 * 160];
    __shared__ float aa[32];
    int t = threadIdx.x;
    for (int i = t; i < 4096; i += 640) ws[i] = lin1_ws[i];
    for (int i = t; i < 1024; i += 640) wv[i] = lin1_wv[i];
    int u = t % 160, q = t / 160;

    for (int chunk = blockIdx.x; chunk < NN / 32; chunk += gridDim.x) {
        int nbase = chunk * 32;
        __syncthreads();
        for (int i = t; i < 32 * 160; i += 640) sv[i] = nf[(size_t)nbase * 160 + i];
        if (t < 32) aa[t] = na[nbase + t];
        __syncthreads();

        if (u < 64) {
            float acc[8];
            #pragma unroll
            for (int k = 0; k < 8; k++) acc[k] = 0.f;
            #pragma unroll
            for (int c = 0; c < 64; c++) {
                float w = ws[c * 64 + u];
                #pragma unroll
                for (int k = 0; k < 8; k++) acc[k] = fmaf(sv[(q * 8 + k) * 160 + c], w, acc[k]);
            }
            #pragma unroll
            for (int k = 0; k < 8; k++) {
                int n = q * 8 + k;
                g_h[(size_t)(nbase + n) * 160 + u] = acc[k] * aa[n] * INV8;
            }
        } else {
            int g = u - 64, d = g / 3, ii = g - d * 3;
            float acc[8];
            #pragma unroll
            for (int k = 0; k < 8; k++) acc[k] = 0.f;
            #pragma unroll
            for (int c = 0; c < 32; c++) {
                float w = wv[c * 32 + d];
                #pragma unroll
                for (int k = 0; k < 8; k++) acc[k] = fmaf(sv[(q * 8 + k) * 160 + 64 + c * 3 + ii], w, acc[k]);
            }
            #pragma unroll
            for (int k = 0; k < 8; k++) {
                int n = q * 8 + k;
                g_h[(size_t)(nbase + n) * 160 + u] = acc[k] * aa[n] * INV_SQRT32;
            }
        }
    }
}

// ---------------- edge kernel (R8 structure + dst-sorted perm consumption) ----------------
#define G_EST   0
#define G_HID   4160
#define G_HSV   8320
#define G_EA    18720
#define G_IDX   18980
#define GROUP_FLOATS 19108
#define W_FLOATS 18432
#define ESMEM_FLOATS (W_FLOATS + 2 * GROUP_FLOATS)
#define ESMEM_BYTES  (ESMEM_FLOATS * 4)

__global__ void __launch_bounds__(1024) edge_kernel(
    const float* __restrict__ edge_scalars, const int* __restrict__ edge_src,
    const int* __restrict__ edge_dst, const float* __restrict__ edge_attr,
    const float* __restrict__ fc_w1, const float* __restrict__ fc_w2)
{
    extern __shared__ float sm[];
    float* w1s = sm;
    float* w2s = sm + 4096;

    int t = threadIdx.x;
    for (int i = t; i < 4096;  i += 1024) w1s[i] = fc_w1[i];
    for (int i = t; i < 14336; i += 1024) w2s[i] = fc_w2[i];
    __syncthreads();

    int wid  = t >> 5;
    int lane = t & 31;
    int g    = wid >> 4;
    int gw   = wid & 15;
    int t2   = t & 511;
    int barid = 1 + g;

    float* gb    = sm + W_FLOATS + g * GROUP_FLOATS;
    float* es_t  = gb + G_EST;     // [c][e] stride 65
    float* hid_t = gb + G_HID;
    float* hsv_t = gb + G_HSV;
    float* ea_t  = gb + G_EA;
    int*   src_sm = (int*)(gb + G_IDX);
    int*   dst_sm = src_sm + 64;

    int njq = (gw < 8) ? 4 : 3;

    for (int tile = blockIdx.x * 2 + g; tile < EE / 64; tile += 296) {
        int base = tile * 64;
        GBAR(barid);

        // ---- phase A: stage 64 dst-sorted edges (via perm, transposed) ----
        {
            #pragma unroll
            for (int m = 0; m < 2; m++) {
                int idx = t2 + m * 512;          // 1024 float4 = 64e x 16 quads
                int e = idx >> 4, c4 = idx & 15;
                int ei = __ldg(&g_perm[base + e]);   // 16 threads same e -> broadcast
                float4 v = reinterpret_cast<const float4*>(edge_scalars)[(size_t)ei * 16 + c4];
                int c = c4 * 4;
                es_t[(c + 0) * 65 + e] = v.x;
                es_t[(c + 1) * 65 + e] = v.y;
                es_t[(c + 2) * 65 + e] = v.z;
                es_t[(c + 3) * 65 + e] = v.w;
            }
            if (t2 < 64) {
                int ei2 = __ldg(&g_perm[base + t2]);
                src_sm[t2] = edge_src[ei2];
                dst_sm[t2] = edge_dst[ei2];
                float4 ea = reinterpret_cast<const float4*>(edge_attr)[ei2];
                ea_t[0 * 65 + t2] = ea.x; ea_t[1 * 65 + t2] = ea.y;
                ea_t[2 * 65 + t2] = ea.z; ea_t[3 * 65 + t2] = ea.w;
            }
        }
        GBAR(barid);

        // ---- phase B: gather h rows + GEMM1 over 2 edge-sets ----
        {
            #pragma unroll
            for (int m = 0; m < 5; m++) {
                int idx = t2 + m * 512;            // 2560 float4s = 64e x 40
                int e = idx / 40, c4 = idx - e * 40;
                float4 v = reinterpret_cast<const float4*>(g_h + (size_t)src_sm[e] * 160)[c4];
                int c = c4 * 4;
                hsv_t[(c + 0) * 65 + e] = v.x;
                hsv_t[(c + 1) * 65 + e] = v.y;
                hsv_t[(c + 2) * 65 + e] = v.z;
                hsv_t[(c + 3) * 65 + e] = v.w;
            }
        }
        {
            float a0x = 0.f, a0y = 0.f, a0z = 0.f, a0w = 0.f;
            float a1x = 0.f, a1y = 0.f, a1z = 0.f, a1w = 0.f;
            #pragma unroll
            for (int c = 0; c < 64; c++) {
                float4 w = *reinterpret_cast<const float4*>(w1s + c * 64 + gw * 4);
                float x0 = es_t[c * 65 + lane];
                float x1 = es_t[c * 65 + 32 + lane];
                a0x = fmaf(x0, w.x, a0x); a0y = fmaf(x0, w.y, a0y);
                a0z = fmaf(x0, w.z, a0z); a0w = fmaf(x0, w.w, a0w);
                a1x = fmaf(x1, w.x, a1x); a1y = fmaf(x1, w.y, a1y);
                a1z = fmaf(x1, w.z, a1z); a1w = fmaf(x1, w.w, a1w);
            }
            hid_t[(gw * 4 + 0) * 65 + lane] = siluf_(a0x * INV8);
            hid_t[(gw * 4 + 1) * 65 + lane] = siluf_(a0y * INV8);
            hid_t[(gw * 4 + 2) * 65 + lane] = siluf_(a0z * INV8);
            hid_t[(gw * 4 + 3) * 65 + lane] = siluf_(a0w * INV8);
            hid_t[(gw * 4 + 0) * 65 + 32 + lane] = siluf_(a1x * INV8);
            hid_t[(gw * 4 + 1) * 65 + 32 + lane] = siluf_(a1y * INV8);
            hid_t[(gw * 4 + 2) * 65 + 32 + lane] = siluf_(a1z * INV8);
            hid_t[(gw * 4 + 3) * 65 + 32 + lane] = siluf_(a1w * INV8);
        }
        GBAR(barid);

        // ---- phase C: GEMM2, all col-quads x 2 edge-sets chunked in registers ----
        float acc[4][2][4];
        #pragma unroll
        for (int q = 0; q < 4; q++)
            #pragma unroll
            for (int s = 0; s < 2; s++)
                #pragma unroll
                for (int k = 0; k < 4; k++) acc[q][s][k] = 0.f;

        #pragma unroll
        for (int cc = 0; cc < 64; cc += 4) {
            float x0[4], x1[4];
            #pragma unroll
            for (int k = 0; k < 4; k++) {
                x0[k] = hid_t[(cc + k) * 65 + lane];
                x1[k] = hid_t[(cc + k) * 65 + 32 + lane];
            }
            #pragma unroll
            for (int q = 0; q < 4; q++) {
                if (q < njq) {
                    int j = (gw + 16 * q) * 4;
                    #pragma unroll
                    for (int k = 0; k < 4; k++) {
                        float4 w = *reinterpret_cast<const float4*>(w2s + (cc + k) * 224 + j);
                        acc[q][0][0] = fmaf(x0[k], w.x, acc[q][0][0]);
                        acc[q][0][1] = fmaf(x0[k], w.y, acc[q][0][1]);
                        acc[q][0][2] = fmaf(x0[k], w.z, acc[q][0][2]);
                        acc[q][0][3] = fmaf(x0[k], w.w, acc[q][0][3]);
                        acc[q][1][0] = fmaf(x1[k], w.x, acc[q][1][0]);
                        acc[q][1][1] = fmaf(x1[k], w.y, acc[q][1][1]);
                        acc[q][1][2] = fmaf(x1[k], w.z, acc[q][1][2]);
                        acc[q][1][3] = fmaf(x1[k], w.w, acc[q][1][3]);
                    }
                }
            }
        }

        // ---- phase D: messages + plain float4 scatter-add (dst-sorted lanes coalesce) ----
        #pragma unroll
        for (int s = 0; s < 2; s++) {
            int e = 32 * s + lane;
            float e0 = ea_t[0 * 65 + e];
            float b0 = ea_t[1 * 65 + e], b1 = ea_t[2 * 65 + e], b2 = ea_t[3 * 65 + e];
            float* R = g_agg + (size_t)dst_sm[e] * 480;
            #define HC(c) hsv_t[(c) * 65 + e]

            for (int q = 0; q < njq; q++) {
                int j = (gw + 16 * q) * 4;
                float scale = INV8;
                if (j >= 192)      scale *= INV_SQRT2;
                else if (j >= 160) scale *= INV_SQRT3;
                float ax = acc[q][s][0] * scale, ay = acc[q][s][1] * scale;
                float az = acc[q][s][2] * scale, aw = acc[q][s][3] * scale;

                if (j < 64) {
                    atomicAdd(reinterpret_cast<float4*>(R + j), make_float4(
                        ax * HC(j) * e0, ay * HC(j + 1) * e0,
                        az * HC(j + 2) * e0, aw * HC(j + 3) * e0));
                } else if (j < 128) {
                    int d = j - 64;
                    float c0 = ax * HC(d), c1 = ay * HC(d + 1), c2 = az * HC(d + 2), c3 = aw * HC(d + 3);
                    float* o = R + 96 + d * 3;
                    atomicAdd(reinterpret_cast<float4*>(o),     make_float4(c0*b0, c0*b1, c0*b2, c1*b0));
                    atomicAdd(reinterpret_cast<float4*>(o + 4), make_float4(c1*b1, c1*b2, c2*b0, c2*b1));
                    atomicAdd(reinterpret_cast<float4*>(o + 8), make_float4(c2*b2, c3*b0, c3*b1, c3*b2));
                } else if (j < 160) {
                    int c = j - 128;
                    int hb = 64 + c * 3;
                    float* o = R + 288 + c * 3;
                    atomicAdd(reinterpret_cast<float4*>(o), make_float4(
                        ax * HC(hb + 0) * e0, ax * HC(hb + 1) * e0,
                        ax * HC(hb + 2) * e0, ay * HC(hb + 3) * e0));
                    atomicAdd(reinterpret_cast<float4*>(o + 4), make_float4(
                        ay * HC(hb + 4) * e0, ay * HC(hb + 5) * e0,
                        az * HC(hb + 6) * e0, az * HC(hb + 7) * e0));
                    atomicAdd(reinterpret_cast<float4*>(o + 8), make_float4(
                        az * HC(hb + 8) * e0, aw * HC(hb + 9) * e0,
                        aw * HC(hb + 10) * e0, aw * HC(hb + 11) * e0));
                } else if (j < 192) {
                    int c = j - 160;
                    int hb = 64 + c * 3;
                    atomicAdd(reinterpret_cast<float4*>(R + 64 + c), make_float4(
                        ax * (HC(hb+0)*b0 + HC(hb+1)*b1 + HC(hb+2)*b2),
                        ay * (HC(hb+3)*b0 + HC(hb+4)*b1 + HC(hb+5)*b2),
                        az * (HC(hb+6)*b0 + HC(hb+7)*b1 + HC(hb+8)*b2),
                        aw * (HC(hb+9)*b0 + HC(hb+10)*b1 + HC(hb+11)*b2)));
                } else {
                    int c = j - 192;
                    int hb = 64 + c * 3;
                    float a0, a1, a2;
                    float* o = R + 384 + c * 3;
                    a0 = HC(hb+0); a1 = HC(hb+1); a2 = HC(hb+2);
                    float x0 = ax*(a1*b2 - a2*b1), x1 = ax*(a2*b0 - a0*b2), x2 = ax*(a0*b1 - a1*b0);
                    a0 = HC(hb+3); a1 = HC(hb+4); a2 = HC(hb+5);
                    float y0 = ay*(a1*b2 - a2*b1), y1 = ay*(a2*b0 - a0*b2), y2 = ay*(a0*b1 - a1*b0);
                    atomicAdd(reinterpret_cast<float4*>(o), make_float4(x0, x1, x2, y0));
                    a0 = HC(hb+6); a1 = HC(hb+7); a2 = HC(hb+8);
                    float z0 = az*(a1*b2 - a2*b1), z1 = az*(a2*b0 - a0*b2), z2 = az*(a0*b1 - a1*b0);
                    atomicAdd(reinterpret_cast<float4*>(o + 4), make_float4(y1, y2, z0, z1));
                    a0 = HC(hb+9); a1 = HC(hb+10); a2 = HC(hb+11);
                    atomicAdd(reinterpret_cast<float4*>(o + 8), make_float4(
                        z2, aw*(a1*b2 - a2*b1), aw*(a2*b0 - a0*b2), aw*(a0*b1 - a1*b0)));
                }
            }
            #undef HC
        }
    }
}

// ---------------- node post ----------------
#define PSMEM_FLOATS 42016
#define PSMEM_BYTES  (PSMEM_FLOATS * 4)

__global__ void __launch_bounds__(768) node_post_kernel(
    const float* __restrict__ nf, const float* __restrict__ na,
    const float* __restrict__ sc_ws, const float* __restrict__ sc_wv,
    const float* __restrict__ lin2_ws, const float* __restrict__ lin2_wv,
    float* __restrict__ out)
{
    extern __shared__ float sm[];
    float* scws  = sm;
    float* l2ws  = sm + 6144;
    float* scwv  = sm + 15360;
    float* l2wv  = sm + 16384;
    float* sv    = sm + 20480;
    float* ag    = sm + 25600;
    float* gates = sm + 40960;
    float* aa    = sm + 41984;

    int t = threadIdx.x;
    for (int i = t; i < 6144; i += 768) scws[i] = sc_ws[i];
    for (int i = t; i < 9216; i += 768) l2ws[i] = lin2_ws[i];
    for (int i = t; i < 1024; i += 768) scwv[i] = sc_wv[i];
    for (int i = t; i < 4096; i += 768) l2wv[i] = lin2_wv[i];
    int u = t % 192, q = t / 192;

    for (int chunk = blockIdx.x; chunk < NN / 32; chunk += gridDim.x) {
        int nbase = chunk * 32;
        __syncthreads();
        for (int i = t; i < 5120; i += 768) sv[i] = nf[(size_t)nbase * 160 + i];
        for (int i = t; i < 15360; i += 768) ag[i] = g_agg[(size_t)nbase * 480 + i];
        if (t < 32) aa[t] = na[nbase + t];
        __syncthreads();

        float pv[8];
        bool is_vec = (u >= 96);
        if (!is_vec) {
            int d = u;
            float acc[8], ac2[8];
            #pragma unroll
            for (int k = 0; k < 8; k++) { acc[k] = 0.f; ac2[k] = 0.f; }
            #pragma unroll
            for (int c = 0; c < 64; c++) {
                float w = scws[c * 96 + d];
                #pragma unroll
                for (int k = 0; k < 8; k++) acc[k] = fmaf(sv[(q * 8 + k) * 160 + c], w, acc[k]);
            }
            #pragma unroll
            for (int c = 0; c < 96; c++) {
                float w = l2ws[c * 96 + d];
                #pragma unroll
                for (int k = 0; k < 8; k++) ac2[k] = fmaf(ag[(q * 8 + k) * 480 + c], w, ac2[k]);
            }
            #pragma unroll
            for (int k = 0; k < 8; k++) {
                int n = q * 8 + k;
                float pre = (acc[k] * INV8 + ac2[k] * (INV_SQRT96 * INV_NN)) * aa[n];
                if (d < 64) out[(size_t)(nbase + n) * 160 + d] = siluf_(pre);
                else        gates[n * 32 + (d - 64)] = sigmoidf_(pre);
            }
        } else {
            int g = u - 96, d = g / 3, ii = g - d * 3;
            float acc[8], ac2[8];
            #pragma unroll
            for (int k = 0; k < 8; k++) { acc[k] = 0.f; ac2[k] = 0.f; }
            #pragma unroll
            for (int c = 0; c < 32; c++) {
                float w = scwv[c * 32 + d];
                #pragma unroll
                for (int k = 0; k < 8; k++) acc[k] = fmaf(sv[(q * 8 + k) * 160 + 64 + c * 3 + ii], w, acc[k]);
            }
            #pragma unroll
            for (int c = 0; c < 128; c++) {
                float w = l2wv[c * 32 + d];
                #pragma unroll
                for (int k = 0; k < 8; k++) ac2[k] = fmaf(ag[(q * 8 + k) * 480 + 96 + c * 3 + ii], w, ac2[k]);
            }
            #pragma unroll
            for (int k = 0; k < 8; k++) {
                int n = q * 8 + k;
                pv[k] = (acc[k] * INV_SQRT32 + ac2[k] * (INV_SQRT128 * INV_NN)) * aa[n];
            }
        }
        __syncthreads();
        if (is_vec) {
            int g = u - 96, d = g / 3;
            #pragma unroll
            for (int k = 0; k < 8; k++) {
                int n = q * 8 + k;
                out[(size_t)(nbase + n) * 160 + 64 + g] = gates[n * 32 + d] * pv[k];
            }
        }
    }
}

// ---------------- launch ----------------
extern "C" void kernel_launch(void* const* d_in, const int* in_sizes, int n_in,
                              void* d_out, int out_size)
{
    const float* nf      = (const float*)d_in[0];
    const float* na      = (const float*)d_in[1];
    const int*   esrc    = (const int*)  d_in[2];
    const int*   edst    = (const int*)  d_in[3];
    const float* eattr   = (const float*)d_in[4];
    const float* escal   = (const float*)d_in[5];
    const float* lin1_ws = (const float*)d_in[6];
    const float* lin1_wv = (const float*)d_in[7];
    const float* fc_w1   = (const float*)d_in[8];
    const float* fc_w2   = (const float*)d_in[9];
    const float* sc_ws   = (const float*)d_in[10];
    const float* sc_wv   = (const float*)d_in[11];
    const float* lin2_ws = (const float*)d_in[12];
    const float* lin2_wv = (const float*)d_in[13];
    float* out = (float*)d_out;

    cudaFuncSetAttribute(edge_kernel,      cudaFuncAttributeMaxDynamicSharedMemorySize, ESMEM_BYTES);
    cudaFuncSetAttribute(node_post_kernel, cudaFuncAttributeMaxDynamicSharedMemorySize, PSMEM_BYTES);

    zero_all_kernel<<<(NN * 120 + 255) / 256, 256>>>();
    hist_kernel<<<(EE + 255) / 256, 256>>>(edst);
    scan_kernel<<<1, 1024>>>();
    scatter_kernel<<<(EE + 255) / 256, 256>>>(edst);
    node_pre_kernel<<<148, 640>>>(nf, na, lin1_ws, lin1_wv);
    edge_kernel<<<148, 1024, ESMEM_BYTES>>>(escal, esrc, edst, eattr, fc_w1, fc_w2);
    node_post_kernel<<<148, 768, PSMEM_BYTES>>>(nf, na, sc_ws, sc_wv, lin2_ws, lin2_wv, out);
}

// round 12
// speedup vs baseline: 1.1029x; 1.1029x over previous
#include <cuda_runtime.h>
#include <cstdint>

#define NN 40000
#define EE 640000

__device__ __align__(16) float g_h[(size_t)NN * 160];
__device__ __align__(16) float g_agg[(size_t)NN * 480];

static constexpr float INV8        = 0.125f;
static constexpr float INV_SQRT32  = 0.17677669529663687f;
static constexpr float INV_SQRT3   = 0.57735026918962576f;
static constexpr float INV_SQRT2   = 0.70710678118654752f;
static constexpr float INV_SQRT96  = 0.10206207261596575f;
static constexpr float INV_SQRT128 = 0.08838834764831845f;
static constexpr float INV_NN      = 0.25f;

__device__ __forceinline__ float sigmoidf_(float x) { return 1.f / (1.f + __expf(-x)); }
__device__ __forceinline__ float siluf_(float x)    { return x / (1.f + __expf(-x)); }

#define GBAR(id) asm volatile("bar.sync %0, 512;" :: "r"(id) : "memory")

__global__ void zero_kernel() {
    size_t i = (size_t)blockIdx.x * blockDim.x + threadIdx.x;
    if (i < (size_t)NN * 120) reinterpret_cast<float4*>(g_agg)[i] = make_float4(0.f, 0.f, 0.f, 0.f);
}
__global__ void dummy_kernel() {}

// ---------------- node pre (unchanged) ----------------
__global__ void __launch_bounds__(640) node_pre_kernel(
    const float* __restrict__ nf, const float* __restrict__ na,
    const float* __restrict__ lin1_ws, const float* __restrict__ lin1_wv)
{
    __shared__ float ws[64 * 64];
    __shared__ float wv[32 * 32];
    __shared__ float sv[32 * 160];
    __shared__ float aa[32];
    int t = threadIdx.x;
    for (int i = t; i < 4096; i += 640) ws[i] = lin1_ws[i];
    for (int i = t; i < 1024; i += 640) wv[i] = lin1_wv[i];
    int u = t % 160, q = t / 160;

    for (int chunk = blockIdx.x; chunk < NN / 32; chunk += gridDim.x) {
        int nbase = chunk * 32;
        __syncthreads();
        for (int i = t; i < 32 * 160; i += 640) sv[i] = nf[(size_t)nbase * 160 + i];
        if (t < 32) aa[t] = na[nbase + t];
        __syncthreads();

        if (u < 64) {
            float acc[8];
            #pragma unroll
            for (int k = 0; k < 8; k++) acc[k] = 0.f;
            #pragma unroll
            for (int c = 0; c < 64; c++) {
                float w = ws[c * 64 + u];
                #pragma unroll
                for (int k = 0; k < 8; k++) acc[k] = fmaf(sv[(q * 8 + k) * 160 + c], w, acc[k]);
            }
            #pragma unroll
            for (int k = 0; k < 8; k++) {
                int n = q * 8 + k;
                g_h[(size_t)(nbase + n) * 160 + u] = acc[k] * aa[n] * INV8;
            }
        } else {
            int g = u - 64, d = g / 3, ii = g - d * 3;
            float acc[8];
            #pragma unroll
            for (int k = 0; k < 8; k++) acc[k] = 0.f;
            #pragma unroll
            for (int c = 0; c < 32; c++) {
                float w = wv[c * 32 + d];
                #pragma unroll
                for (int k = 0; k < 8; k++) acc[k] = fmaf(sv[(q * 8 + k) * 160 + 64 + c * 3 + ii], w, acc[k]);
            }
            #pragma unroll
            for (int k = 0; k < 8; k++) {
                int n = q * 8 + k;
                g_h[(size_t)(nbase + n) * 160 + u] = acc[k] * aa[n] * INV_SQRT32;
            }
        }
    }
}

// ---------------- edge kernel: row-major smem, all accesses float4 ----------------
// layouts (float offsets within group):
//   es  [e][c] stride 68 (17 float4, odd -> conflict-free)   64*68  = 4352
//   hid [e][c] stride 68                                      64*68  = 4352
//   hsv [e][c] stride 164 (41 float4)                         64*164 = 10496
//   ea  [e][4]                                                 256
//   idx src[64] dst[64]                                        128
#define G_ES    0
#define G_HID   4352
#define G_HSV   8704
#define G_EA    19200
#define G_IDX   19456
#define GROUP_FLOATS 19584
#define W_FLOATS 18432
#define ESMEM_FLOATS (W_FLOATS + 2 * GROUP_FLOATS)
#define ESMEM_BYTES  (ESMEM_FLOATS * 4)

__global__ void __launch_bounds__(1024) edge_kernel(
    const float* __restrict__ edge_scalars, const int* __restrict__ edge_src,
    const int* __restrict__ edge_dst, const float* __restrict__ edge_attr,
    const float* __restrict__ fc_w1, const float* __restrict__ fc_w2)
{
    extern __shared__ float sm[];
    float* w1s = sm;
    float* w2s = sm + 4096;

    int t = threadIdx.x;
    for (int i = t; i < 4096;  i += 1024) w1s[i] = fc_w1[i];
    for (int i = t; i < 14336; i += 1024) w2s[i] = fc_w2[i];
    __syncthreads();

    int wid  = t >> 5;
    int lane = t & 31;
    int g    = wid >> 4;
    int gw   = wid & 15;
    int t2   = t & 511;
    int barid = 1 + g;

    float* gb   = sm + W_FLOATS + g * GROUP_FLOATS;
    float* es   = gb + G_ES;
    float* hid  = gb + G_HID;
    float* hsv  = gb + G_HSV;
    float* ea   = gb + G_EA;
    int* src_sm = (int*)(gb + G_IDX);
    int* dst_sm = src_sm + 64;

    int njq = (gw < 8) ? 4 : 3;

    for (int tile = blockIdx.x * 2 + g; tile < EE / 64; tile += 296) {
        int base = tile * 64;
        GBAR(barid);

        // ---- phase A: stage 64 edges (row-major, straight float4) ----
        #pragma unroll
        for (int m = 0; m < 2; m++) {
            int idx = t2 + m * 512;                 // 1024 float4 = 64e x 16
            int e = idx >> 4, c4 = idx & 15;
            float4 v = reinterpret_cast<const float4*>(edge_scalars + (size_t)base * 64)[idx];
            *reinterpret_cast<float4*>(es + e * 68 + c4 * 4) = v;
        }
        if (t2 < 64) {
            src_sm[t2] = edge_src[base + t2];
            dst_sm[t2] = edge_dst[base + t2];
            *reinterpret_cast<float4*>(ea + t2 * 4) =
                reinterpret_cast<const float4*>(edge_attr)[base + t2];
        }
        GBAR(barid);

        // ---- phase B: gather h rows (row-major) + GEMM1 ----
        #pragma unroll
        for (int m = 0; m < 5; m++) {
            int idx = t2 + m * 512;                 // 2560 float4 = 64e x 40
            int e = idx / 40, c4 = idx - e * 40;
            float4 v = reinterpret_cast<const float4*>(g_h + (size_t)src_sm[e] * 160)[c4];
            *reinterpret_cast<float4*>(hsv + e * 164 + c4 * 4) = v;
        }
        {
            float a0[4] = {0.f, 0.f, 0.f, 0.f};
            float a1[4] = {0.f, 0.f, 0.f, 0.f};
            #pragma unroll
            for (int cc = 0; cc < 64; cc += 4) {
                float4 x0 = *reinterpret_cast<const float4*>(es + lane * 68 + cc);
                float4 x1 = *reinterpret_cast<const float4*>(es + (lane + 32) * 68 + cc);
                float xa0[4] = {x0.x, x0.y, x0.z, x0.w};
                float xa1[4] = {x1.x, x1.y, x1.z, x1.w};
                #pragma unroll
                for (int k = 0; k < 4; k++) {
                    float4 w = *reinterpret_cast<const float4*>(w1s + (cc + k) * 64 + gw * 4);
                    a0[0] = fmaf(xa0[k], w.x, a0[0]); a0[1] = fmaf(xa0[k], w.y, a0[1]);
                    a0[2] = fmaf(xa0[k], w.z, a0[2]); a0[3] = fmaf(xa0[k], w.w, a0[3]);
                    a1[0] = fmaf(xa1[k], w.x, a1[0]); a1[1] = fmaf(xa1[k], w.y, a1[1]);
                    a1[2] = fmaf(xa1[k], w.z, a1[2]); a1[3] = fmaf(xa1[k], w.w, a1[3]);
                }
            }
            *reinterpret_cast<float4*>(hid + lane * 68 + gw * 4) = make_float4(
                siluf_(a0[0] * INV8), siluf_(a0[1] * INV8), siluf_(a0[2] * INV8), siluf_(a0[3] * INV8));
            *reinterpret_cast<float4*>(hid + (lane + 32) * 68 + gw * 4) = make_float4(
                siluf_(a1[0] * INV8), siluf_(a1[1] * INV8), siluf_(a1[2] * INV8), siluf_(a1[3] * INV8));
        }
        GBAR(barid);

        // ---- phase C: GEMM2, quads {gw, gw+16, gw+32, gw+48} x 2 esets ----
        float acc[4][2][4];
        #pragma unroll
        for (int q = 0; q < 4; q++)
            #pragma unroll
            for (int s = 0; s < 2; s++)
                #pragma unroll
                for (int k = 0; k < 4; k++) acc[q][s][k] = 0.f;

        #pragma unroll
        for (int cc = 0; cc < 64; cc += 4) {
            float4 x0 = *reinterpret_cast<const float4*>(hid + lane * 68 + cc);
            float4 x1 = *reinterpret_cast<const float4*>(hid + (lane + 32) * 68 + cc);
            float xa0[4] = {x0.x, x0.y, x0.z, x0.w};
            float xa1[4] = {x1.x, x1.y, x1.z, x1.w};
            #pragma unroll
            for (int q = 0; q < 4; q++) {
                if (q < njq) {
                    int j = (gw + 16 * q) * 4;
                    #pragma unroll
                    for (int k = 0; k < 4; k++) {
                        float4 w = *reinterpret_cast<const float4*>(w2s + (cc + k) * 224 + j);
                        acc[q][0][0] = fmaf(xa0[k], w.x, acc[q][0][0]);
                        acc[q][0][1] = fmaf(xa0[k], w.y, acc[q][0][1]);
                        acc[q][0][2] = fmaf(xa0[k], w.z, acc[q][0][2]);
                        acc[q][0][3] = fmaf(xa0[k], w.w, acc[q][0][3]);
                        acc[q][1][0] = fmaf(xa1[k], w.x, acc[q][1][0]);
                        acc[q][1][1] = fmaf(xa1[k], w.y, acc[q][1][1]);
                        acc[q][1][2] = fmaf(xa1[k], w.z, acc[q][1][2]);
                        acc[q][1][3] = fmaf(xa1[k], w.w, acc[q][1][3]);
                    }
                }
            }
        }

        // ---- phase D: messages, all HC reads as float4, arms warp-uniform ----
        #pragma unroll
        for (int s = 0; s < 2; s++) {
            int e = 32 * s + lane;
            float4 eav = *reinterpret_cast<const float4*>(ea + e * 4);
            float e0 = eav.x, b0 = eav.y, b1 = eav.z, b2 = eav.w;
            float* R = g_agg + (size_t)dst_sm[e] * 480;
            const float* H = hsv + e * 164;

            // shared h_s quad for m_s1 (q=0) and m_v1 (q=1): both at offset 4*gw
            float4 hs = *reinterpret_cast<const float4*>(H + 4 * gw);
            {   // m_s1
                float ax = acc[0][s][0] * INV8, ay = acc[0][s][1] * INV8;
                float az = acc[0][s][2] * INV8, aw = acc[0][s][3] * INV8;
                atomicAdd(reinterpret_cast<float4*>(R + 4 * gw), make_float4(
                    ax * hs.x * e0, ay * hs.y * e0, az * hs.z * e0, aw * hs.w * e0));
            }
            {   // m_v1
                float ax = acc[1][s][0] * INV8, ay = acc[1][s][1] * INV8;
                float az = acc[1][s][2] * INV8, aw = acc[1][s][3] * INV8;
                float c0 = ax * hs.x, c1 = ay * hs.y, c2 = az * hs.z, c3 = aw * hs.w;
                float* o = R + 96 + 12 * gw;
                atomicAdd(reinterpret_cast<float4*>(o),     make_float4(c0*b0, c0*b1, c0*b2, c1*b0));
                atomicAdd(reinterpret_cast<float4*>(o + 4), make_float4(c1*b1, c1*b2, c2*b0, c2*b1));
                atomicAdd(reinterpret_cast<float4*>(o + 8), make_float4(c2*b2, c3*b0, c3*b1, c3*b2));
            }
            if (gw < 8) {
                // m_v2 (q=2) and m_v3 (q=3) share ev block at hb = 64 + 12*gw
                int hb = 64 + 12 * gw;
                float4 h0 = *reinterpret_cast<const float4*>(H + hb);
                float4 h1 = *reinterpret_cast<const float4*>(H + hb + 4);
                float4 h2 = *reinterpret_cast<const float4*>(H + hb + 8);
                float A[12] = {h0.x, h0.y, h0.z, h0.w, h1.x, h1.y, h1.z, h1.w, h2.x, h2.y, h2.z, h2.w};
                {   // m_v2 = w3 * ev * e0 -> R+288+12gw
                    float ax = acc[2][s][0] * INV8, ay = acc[2][s][1] * INV8;
                    float az = acc[2][s][2] * INV8, aw = acc[2][s][3] * INV8;
                    float* o = R + 288 + 12 * gw;
                    atomicAdd(reinterpret_cast<float4*>(o), make_float4(
                        ax*A[0]*e0, ax*A[1]*e0, ax*A[2]*e0, ay*A[3]*e0));
                    atomicAdd(reinterpret_cast<float4*>(o + 4), make_float4(
                        ay*A[4]*e0, ay*A[5]*e0, az*A[6]*e0, az*A[7]*e0));
                    atomicAdd(reinterpret_cast<float4*>(o + 8), make_float4(
                        az*A[8]*e0, aw*A[9]*e0, aw*A[10]*e0, aw*A[11]*e0));
                }
                {   // m_v3 = w5 * cross(ev, e1) / sqrt2 -> R+384+12gw
                    float sc = INV8 * INV_SQRT2;
                    float ax = acc[3][s][0] * sc, ay = acc[3][s][1] * sc;
                    float az = acc[3][s][2] * sc, aw = acc[3][s][3] * sc;
                    float* o = R + 384 + 12 * gw;
                    atomicAdd(reinterpret_cast<float4*>(o), make_float4(
                        ax*(A[1]*b2 - A[2]*b1), ax*(A[2]*b0 - A[0]*b2),
                        ax*(A[0]*b1 - A[1]*b0), ay*(A[4]*b2 - A[5]*b1)));
                    atomicAdd(reinterpret_cast<float4*>(o + 4), make_float4(
                        ay*(A[5]*b0 - A[3]*b2), ay*(A[3]*b1 - A[4]*b0),
                        az*(A[7]*b2 - A[8]*b1), az*(A[8]*b0 - A[6]*b2)));
                    atomicAdd(reinterpret_cast<float4*>(o + 8), make_float4(
                        az*(A[6]*b1 - A[7]*b0), aw*(A[10]*b2 - A[11]*b1),
                        aw*(A[11]*b0 - A[9]*b2), aw*(A[9]*b1 - A[10]*b0)));
                }
            } else {
                // m_s2 (q=2): c = 4gw-32, hb = 12gw-32, scale /sqrt3 -> R+64+c
                int c = 4 * gw - 32;
                int hb = 64 + c * 3;
                float4 h0 = *reinterpret_cast<const float4*>(H + hb);
                float4 h1 = *reinterpret_cast<const float4*>(H + hb + 4);
                float4 h2 = *reinterpret_cast<const float4*>(H + hb + 8);
                float A[12] = {h0.x, h0.y, h0.z, h0.w, h1.x, h1.y, h1.z, h1.w, h2.x, h2.y, h2.z, h2.w};
                float sc = INV8 * INV_SQRT3;
                float ax = acc[2][s][0] * sc, ay = acc[2][s][1] * sc;
                float az = acc[2][s][2] * sc, aw = acc[2][s][3] * sc;
                atomicAdd(reinterpret_cast<float4*>(R + 64 + c), make_float4(
                    ax * (A[0]*b0 + A[1]*b1 + A[2]*b2),
                    ay * (A[3]*b0 + A[4]*b1 + A[5]*b2),
                    az * (A[6]*b0 + A[7]*b1 + A[8]*b2),
                    aw * (A[9]*b0 + A[10]*b1 + A[11]*b2)));
            }
        }
    }
}

// ---------------- node post (unchanged) ----------------
#define PSMEM_FLOATS 42016
#define PSMEM_BYTES  (PSMEM_FLOATS * 4)

__global__ void __launch_bounds__(768) node_post_kernel(
    const float* __restrict__ nf, const float* __restrict__ na,
    const float* __restrict__ sc_ws, const float* __restrict__ sc_wv,
    const float* __restrict__ lin2_ws, const float* __restrict__ lin2_wv,
    float* __restrict__ out)
{
    extern __shared__ float sm[];
    float* scws  = sm;
    float* l2ws  = sm + 6144;
    float* scwv  = sm + 15360;
    float* l2wv  = sm + 16384;
    float* sv    = sm + 20480;
    float* ag    = sm + 25600;
    float* gates = sm + 40960;
    float* aa    = sm + 41984;

    int t = threadIdx.x;
    for (int i = t; i < 6144; i += 768) scws[i] = sc_ws[i];
    for (int i = t; i < 9216; i += 768) l2ws[i] = lin2_ws[i];
    for (int i = t; i < 1024; i += 768) scwv[i] = sc_wv[i];
    for (int i = t; i < 4096; i += 768) l2wv[i] = lin2_wv[i];
    int u = t % 192, q = t / 192;

    for (int chunk = blockIdx.x; chunk < NN / 32; chunk += gridDim.x) {
        int nbase = chunk * 32;
        __syncthreads();
        for (int i = t; i < 5120; i += 768) sv[i] = nf[(size_t)nbase * 160 + i];
        for (int i = t; i < 15360; i += 768) ag[i] = g_agg[(size_t)nbase * 480 + i];
        if (t < 32) aa[t] = na[nbase + t];
        __syncthreads();

        float pv[8];
        bool is_vec = (u >= 96);
        if (!is_vec) {
            int d = u;
            float acc[8], ac2[8];
            #pragma unroll
            for (int k = 0; k < 8; k++) { acc[k] = 0.f; ac2[k] = 0.f; }
            #pragma unroll
            for (int c = 0; c < 64; c++) {
                float w = scws[c * 96 + d];
                #pragma unroll
                for (int k = 0; k < 8; k++) acc[k] = fmaf(sv[(q * 8 + k) * 160 + c], w, acc[k]);
            }
            #pragma unroll
            for (int c = 0; c < 96; c++) {
                float w = l2ws[c * 96 + d];
                #pragma unroll
                for (int k = 0; k < 8; k++) ac2[k] = fmaf(ag[(q * 8 + k) * 480 + c], w, ac2[k]);
            }
            #pragma unroll
            for (int k = 0; k < 8; k++) {
                int n = q * 8 + k;
                float pre = (acc[k] * INV8 + ac2[k] * (INV_SQRT96 * INV_NN)) * aa[n];
                if (d < 64) out[(size_t)(nbase + n) * 160 + d] = siluf_(pre);
                else        gates[n * 32 + (d - 64)] = sigmoidf_(pre);
            }
        } else {
            int g = u - 96, d = g / 3, ii = g - d * 3;
            float acc[8], ac2[8];
            #pragma unroll
            for (int k = 0; k < 8; k++) { acc[k] = 0.f; ac2[k] = 0.f; }
            #pragma unroll
            for (int c = 0; c < 32; c++) {
                float w = scwv[c * 32 + d];
                #pragma unroll
                for (int k = 0; k < 8; k++) acc[k] = fmaf(sv[(q * 8 + k) * 160 + 64 + c * 3 + ii], w, acc[k]);
            }
            #pragma unroll
            for (int c = 0; c < 128; c++) {
                float w = l2wv[c * 32 + d];
                #pragma unroll
                for (int k = 0; k < 8; k++) ac2[k] = fmaf(ag[(q * 8 + k) * 480 + 96 + c * 3 + ii], w, ac2[k]);
            }
            #pragma unroll
            for (int k = 0; k < 8; k++) {
                int n = q * 8 + k;
                pv[k] = (acc[k] * INV_SQRT32 + ac2[k] * (INV_SQRT128 * INV_NN)) * aa[n];
            }
        }
        __syncthreads();
        if (is_vec) {
            int g = u - 96, d = g / 3;
            #pragma unroll
            for (int k = 0; k < 8; k++) {
                int n = q * 8 + k;
                out[(size_t)(nbase + n) * 160 + 64 + g] = gates[n * 32 + d] * pv[k];
            }
        }
    }
}

// ---------------- launch ----------------
extern "C" void kernel_launch(void* const* d_in, const int* in_sizes, int n_in,
                              void* d_out, int out_size)
{
    const float* nf      = (const float*)d_in[0];
    const float* na      = (const float*)d_in[1];
    const int*   esrc    = (const int*)  d_in[2];
    const int*   edst    = (const int*)  d_in[3];
    const float* eattr   = (const float*)d_in[4];
    const float* escal   = (const float*)d_in[5];
    const float* lin1_ws = (const float*)d_in[6];
    const float* lin1_wv = (const float*)d_in[7];
    const float* fc_w1   = (const float*)d_in[8];
    const float* fc_w2   = (const float*)d_in[9];
    const float* sc_ws   = (const float*)d_in[10];
    const float* sc_wv   = (const float*)d_in[11];
    const float* lin2_ws = (const float*)d_in[12];
    const float* lin2_wv = (const float*)d_in[13];
    float* out = (float*)d_out;

    cudaFuncSetAttribute(edge_kernel,      cudaFuncAttributeMaxDynamicSharedMemorySize, ESMEM_BYTES);
    cudaFuncSetAttribute(node_post_kernel, cudaFuncAttributeMaxDynamicSharedMemorySize, PSMEM_BYTES);

    zero_kernel<<<(NN * 120 + 255) / 256, 256>>>();            // idx 0
    node_pre_kernel<<<148, 640>>>(nf, na, lin1_ws, lin1_wv);   // idx 1
    dummy_kernel<<<1, 32>>>();                                 // idx 2 (steer ncu)
    edge_kernel<<<148, 1024, ESMEM_BYTES>>>(escal, esrc, edst, eattr, fc_w1, fc_w2);  // idx 3 <- profiled
    node_post_kernel<<<148, 768, PSMEM_BYTES>>>(nf, na, sc_ws, sc_wv, lin2_ws, lin2_wv, out);
}

// round 14
// speedup vs baseline: 1.1344x; 1.0285x over previous
#include <cuda_runtime.h>
#include <cstdint>

#define NN 40000
#define EE 640000

__device__ __align__(16) float g_h[(size_t)NN * 160];
__device__ __align__(16) float g_agg[(size_t)NN * 480];
__device__ __align__(16) float g_gates[(size_t)NN * 32];

static constexpr float INV8        = 0.125f;
static constexpr float INV_SQRT32  = 0.17677669529663687f;
static constexpr float INV_SQRT3   = 0.57735026918962576f;
static constexpr float INV_SQRT2   = 0.70710678118654752f;
static constexpr float INV_SQRT96  = 0.10206207261596575f;
static constexpr float INV_SQRT128 = 0.08838834764831845f;
static constexpr float INV_NN      = 0.25f;

__device__ __forceinline__ float sigmoidf_(float x) { return 1.f / (1.f + __expf(-x)); }
__device__ __forceinline__ float siluf_(float x)    { return x / (1.f + __expf(-x)); }

#define GBAR(id) asm volatile("bar.sync %0, 512;" :: "r"(id) : "memory")

__global__ void zero_kernel() {
    size_t i = (size_t)blockIdx.x * blockDim.x + threadIdx.x;
    if (i < (size_t)NN * 120) reinterpret_cast<float4*>(g_agg)[i] = make_float4(0.f, 0.f, 0.f, 0.f);
}
__global__ void dummy_kernel() {}

// ---------------- node pre (2 CTAs/SM) ----------------
__global__ void __launch_bounds__(640, 2) node_pre_kernel(
    const float* __restrict__ nf, const float* __restrict__ na,
    const float* __restrict__ lin1_ws, const float* __restrict__ lin1_wv)
{
    __shared__ float ws[64 * 64];
    __shared__ float wv[32 * 32];
    __shared__ float sv[32 * 160];
    __shared__ float aa[32];
    int t = threadIdx.x;
    for (int i = t; i < 4096; i += 640) ws[i] = lin1_ws[i];
    for (int i = t; i < 1024; i += 640) wv[i] = lin1_wv[i];
    int u = t % 160, q = t / 160;

    for (int chunk = blockIdx.x; chunk < NN / 32; chunk += gridDim.x) {
        int nbase = chunk * 32;
        __syncthreads();
        for (int i = t; i < 32 * 160; i += 640) sv[i] = nf[(size_t)nbase * 160 + i];
        if (t < 32) aa[t] = na[nbase + t];
        __syncthreads();

        if (u < 64) {
            float acc[8];
            #pragma unroll
            for (int k = 0; k < 8; k++) acc[k] = 0.f;
            #pragma unroll
            for (int c = 0; c < 64; c++) {
                float w = ws[c * 64 + u];
                #pragma unroll
                for (int k = 0; k < 8; k++) acc[k] = fmaf(sv[(q * 8 + k) * 160 + c], w, acc[k]);
            }
            #pragma unroll
            for (int k = 0; k < 8; k++) {
                int n = q * 8 + k;
                g_h[(size_t)(nbase + n) * 160 + u] = acc[k] * aa[n] * INV8;
            }
        } else {
            int g = u - 64, d = g / 3, ii = g - d * 3;
            float acc[8];
            #pragma unroll
            for (int k = 0; k < 8; k++) acc[k] = 0.f;
            #pragma unroll
            for (int c = 0; c < 32; c++) {
                float w = wv[c * 32 + d];
                #pragma unroll
                for (int k = 0; k < 8; k++) acc[k] = fmaf(sv[(q * 8 + k) * 160 + 64 + c * 3 + ii], w, acc[k]);
            }
            #pragma unroll
            for (int k = 0; k < 8; k++) {
                int n = q * 8 + k;
                g_h[(size_t)(nbase + n) * 160 + u] = acc[k] * aa[n] * INV_SQRT32;
            }
        }
    }
}

// ---------------- edge kernel (unchanged from R12, 1333us baseline) ----------------
#define G_ES    0
#define G_HID   4352
#define G_HSV   8704
#define G_EA    19200
#define G_IDX   19456
#define GROUP_FLOATS 19584
#define W_FLOATS 18432
#define ESMEM_FLOATS (W_FLOATS + 2 * GROUP_FLOATS)
#define ESMEM_BYTES  (ESMEM_FLOATS * 4)

__global__ void __launch_bounds__(1024) edge_kernel(
    const float* __restrict__ edge_scalars, const int* __restrict__ edge_src,
    const int* __restrict__ edge_dst, const float* __restrict__ edge_attr,
    const float* __restrict__ fc_w1, const float* __restrict__ fc_w2)
{
    extern __shared__ float sm[];
    float* w1s = sm;
    float* w2s = sm + 4096;

    int t = threadIdx.x;
    for (int i = t; i < 4096;  i += 1024) w1s[i] = fc_w1[i];
    for (int i = t; i < 14336; i += 1024) w2s[i] = fc_w2[i];
    __syncthreads();

    int wid  = t >> 5;
    int lane = t & 31;
    int g    = wid >> 4;
    int gw   = wid & 15;
    int t2   = t & 511;
    int barid = 1 + g;

    float* gb   = sm + W_FLOATS + g * GROUP_FLOATS;
    float* es   = gb + G_ES;
    float* hid  = gb + G_HID;
    float* hsv  = gb + G_HSV;
    float* ea   = gb + G_EA;
    int* src_sm = (int*)(gb + G_IDX);
    int* dst_sm = src_sm + 64;

    int njq = (gw < 8) ? 4 : 3;

    for (int tile = blockIdx.x * 2 + g; tile < EE / 64; tile += 296) {
        int base = tile * 64;
        GBAR(barid);

        #pragma unroll
        for (int m = 0; m < 2; m++) {
            int idx = t2 + m * 512;
            int e = idx >> 4, c4 = idx & 15;
            float4 v = reinterpret_cast<const float4*>(edge_scalars + (size_t)base * 64)[idx];
            *reinterpret_cast<float4*>(es + e * 68 + c4 * 4) = v;
        }
        if (t2 < 64) {
            src_sm[t2] = edge_src[base + t2];
            dst_sm[t2] = edge_dst[base + t2];
            *reinterpret_cast<float4*>(ea + t2 * 4) =
                reinterpret_cast<const float4*>(edge_attr)[base + t2];
        }
        GBAR(barid);

        #pragma unroll
        for (int m = 0; m < 5; m++) {
            int idx = t2 + m * 512;
            int e = idx / 40, c4 = idx - e * 40;
            float4 v = reinterpret_cast<const float4*>(g_h + (size_t)src_sm[e] * 160)[c4];
            *reinterpret_cast<float4*>(hsv + e * 164 + c4 * 4) = v;
        }
        {
            float a0[4] = {0.f, 0.f, 0.f, 0.f};
            float a1[4] = {0.f, 0.f, 0.f, 0.f};
            #pragma unroll
            for (int cc = 0; cc < 64; cc += 4) {
                float4 x0 = *reinterpret_cast<const float4*>(es + lane * 68 + cc);
                float4 x1 = *reinterpret_cast<const float4*>(es + (lane + 32) * 68 + cc);
                float xa0[4] = {x0.x, x0.y, x0.z, x0.w};
                float xa1[4] = {x1.x, x1.y, x1.z, x1.w};
                #pragma unroll
                for (int k = 0; k < 4; k++) {
                    float4 w = *reinterpret_cast<const float4*>(w1s + (cc + k) * 64 + gw * 4);
                    a0[0] = fmaf(xa0[k], w.x, a0[0]); a0[1] = fmaf(xa0[k], w.y, a0[1]);
                    a0[2] = fmaf(xa0[k], w.z, a0[2]); a0[3] = fmaf(xa0[k], w.w, a0[3]);
                    a1[0] = fmaf(xa1[k], w.x, a1[0]); a1[1] = fmaf(xa1[k], w.y, a1[1]);
                    a1[2] = fmaf(xa1[k], w.z, a1[2]); a1[3] = fmaf(xa1[k], w.w, a1[3]);
                }
            }
            *reinterpret_cast<float4*>(hid + lane * 68 + gw * 4) = make_float4(
                siluf_(a0[0] * INV8), siluf_(a0[1] * INV8), siluf_(a0[2] * INV8), siluf_(a0[3] * INV8));
            *reinterpret_cast<float4*>(hid + (lane + 32) * 68 + gw * 4) = make_float4(
                siluf_(a1[0] * INV8), siluf_(a1[1] * INV8), siluf_(a1[2] * INV8), siluf_(a1[3] * INV8));
        }
        GBAR(barid);

        float acc[4][2][4];
        #pragma unroll
        for (int q = 0; q < 4; q++)
            #pragma unroll
            for (int s = 0; s < 2; s++)
                #pragma unroll
                for (int k = 0; k < 4; k++) acc[q][s][k] = 0.f;

        #pragma unroll
        for (int cc = 0; cc < 64; cc += 4) {
            float4 x0 = *reinterpret_cast<const float4*>(hid + lane * 68 + cc);
            float4 x1 = *reinterpret_cast<const float4*>(hid + (lane + 32) * 68 + cc);
            float xa0[4] = {x0.x, x0.y, x0.z, x0.w};
            float xa1[4] = {x1.x, x1.y, x1.z, x1.w};
            #pragma unroll
            for (int q = 0; q < 4; q++) {
                if (q < njq) {
                    int j = (gw + 16 * q) * 4;
                    #pragma unroll
                    for (int k = 0; k < 4; k++) {
                        float4 w = *reinterpret_cast<const float4*>(w2s + (cc + k) * 224 + j);
                        acc[q][0][0] = fmaf(xa0[k], w.x, acc[q][0][0]);
                        acc[q][0][1] = fmaf(xa0[k], w.y, acc[q][0][1]);
                        acc[q][0][2] = fmaf(xa0[k], w.z, acc[q][0][2]);
                        acc[q][0][3] = fmaf(xa0[k], w.w, acc[q][0][3]);
                        acc[q][1][0] = fmaf(xa1[k], w.x, acc[q][1][0]);
                        acc[q][1][1] = fmaf(xa1[k], w.y, acc[q][1][1]);
                        acc[q][1][2] = fmaf(xa1[k], w.z, acc[q][1][2]);
                        acc[q][1][3] = fmaf(xa1[k], w.w, acc[q][1][3]);
                    }
                }
            }
        }

        #pragma unroll
        for (int s = 0; s < 2; s++) {
            int e = 32 * s + lane;
            float4 eav = *reinterpret_cast<const float4*>(ea + e * 4);
            float e0 = eav.x, b0 = eav.y, b1 = eav.z, b2 = eav.w;
            float* R = g_agg + (size_t)dst_sm[e] * 480;
            const float* H = hsv + e * 164;

            float4 hs = *reinterpret_cast<const float4*>(H + 4 * gw);
            {
                float ax = acc[0][s][0] * INV8, ay = acc[0][s][1] * INV8;
                float az = acc[0][s][2] * INV8, aw = acc[0][s][3] * INV8;
                atomicAdd(reinterpret_cast<float4*>(R + 4 * gw), make_float4(
                    ax * hs.x * e0, ay * hs.y * e0, az * hs.z * e0, aw * hs.w * e0));
            }
            {
                float ax = acc[1][s][0] * INV8, ay = acc[1][s][1] * INV8;
                float az = acc[1][s][2] * INV8, aw = acc[1][s][3] * INV8;
                float c0 = ax * hs.x, c1 = ay * hs.y, c2 = az * hs.z, c3 = aw * hs.w;
                float* o = R + 96 + 12 * gw;
                atomicAdd(reinterpret_cast<float4*>(o),     make_float4(c0*b0, c0*b1, c0*b2, c1*b0));
                atomicAdd(reinterpret_cast<float4*>(o + 4), make_float4(c1*b1, c1*b2, c2*b0, c2*b1));
                atomicAdd(reinterpret_cast<float4*>(o + 8), make_float4(c2*b2, c3*b0, c3*b1, c3*b2));
            }
            if (gw < 8) {
                int hb = 64 + 12 * gw;
                float4 h0 = *reinterpret_cast<const float4*>(H + hb);
                float4 h1 = *reinterpret_cast<const float4*>(H + hb + 4);
                float4 h2 = *reinterpret_cast<const float4*>(H + hb + 8);
                float A[12] = {h0.x, h0.y, h0.z, h0.w, h1.x, h1.y, h1.z, h1.w, h2.x, h2.y, h2.z, h2.w};
                {
                    float ax = acc[2][s][0] * INV8, ay = acc[2][s][1] * INV8;
                    float az = acc[2][s][2] * INV8, aw = acc[2][s][3] * INV8;
                    float* o = R + 288 + 12 * gw;
                    atomicAdd(reinterpret_cast<float4*>(o), make_float4(
                        ax*A[0]*e0, ax*A[1]*e0, ax*A[2]*e0, ay*A[3]*e0));
                    atomicAdd(reinterpret_cast<float4*>(o + 4), make_float4(
                        ay*A[4]*e0, ay*A[5]*e0, az*A[6]*e0, az*A[7]*e0));
                    atomicAdd(reinterpret_cast<float4*>(o + 8), make_float4(
                        az*A[8]*e0, aw*A[9]*e0, aw*A[10]*e0, aw*A[11]*e0));
                }
                {
                    float sc = INV8 * INV_SQRT2;
                    float ax = acc[3][s][0] * sc, ay = acc[3][s][1] * sc;
                    float az = acc[3][s][2] * sc, aw = acc[3][s][3] * sc;
                    float* o = R + 384 + 12 * gw;
                    atomicAdd(reinterpret_cast<float4*>(o), make_float4(
                        ax*(A[1]*b2 - A[2]*b1), ax*(A[2]*b0 - A[0]*b2),
                        ax*(A[0]*b1 - A[1]*b0), ay*(A[4]*b2 - A[5]*b1)));
                    atomicAdd(reinterpret_cast<float4*>(o + 4), make_float4(
                        ay*(A[5]*b0 - A[3]*b2), ay*(A[3]*b1 - A[4]*b0),
                        az*(A[7]*b2 - A[8]*b1), az*(A[8]*b0 - A[6]*b2)));
                    atomicAdd(reinterpret_cast<float4*>(o + 8), make_float4(
                        az*(A[6]*b1 - A[7]*b0), aw*(A[10]*b2 - A[11]*b1),
                        aw*(A[11]*b0 - A[9]*b2), aw*(A[9]*b1 - A[10]*b0)));
                }
            } else {
                int c = 4 * gw - 32;
                int hb = 64 + c * 3;
                float4 h0 = *reinterpret_cast<const float4*>(H + hb);
                float4 h1 = *reinterpret_cast<const float4*>(H + hb + 4);
                float4 h2 = *reinterpret_cast<const float4*>(H + hb + 8);
                float A[12] = {h0.x, h0.y, h0.z, h0.w, h1.x, h1.y, h1.z, h1.w, h2.x, h2.y, h2.z, h2.w};
                float sc = INV8 * INV_SQRT3;
                float ax = acc[2][s][0] * sc, ay = acc[2][s][1] * sc;
                float az = acc[2][s][2] * sc, aw = acc[2][s][3] * sc;
                atomicAdd(reinterpret_cast<float4*>(R + 64 + c), make_float4(
                    ax * (A[0]*b0 + A[1]*b1 + A[2]*b2),
                    ay * (A[3]*b0 + A[4]*b1 + A[5]*b2),
                    az * (A[6]*b0 + A[7]*b1 + A[8]*b2),
                    aw * (A[9]*b0 + A[10]*b1 + A[11]*b2)));
            }
        }
    }
}

// ---------------- node post, split: scalar kernel (2 CTAs/SM) ----------------
#define NPS_FLOATS 25664
#define NPS_BYTES (NPS_FLOATS * 4)
__global__ void __launch_bounds__(768, 2) np_scalar_kernel(
    const float* __restrict__ nf, const float* __restrict__ na,
    const float* __restrict__ sc_ws, const float* __restrict__ lin2_ws,
    float* __restrict__ out)
{
    extern __shared__ float sm[];
    float* scws = sm;             // 6144
    float* l2ws = sm + 6144;      // 9216
    float* svs  = sm + 15360;     // 4096 (64x64)
    float* ags  = sm + 19456;     // 6144 (64x96)
    float* aa   = sm + 25600;     // 64

    int t = threadIdx.x;
    for (int i = t; i < 6144; i += 768) scws[i] = sc_ws[i];
    for (int i = t; i < 9216; i += 768) l2ws[i] = lin2_ws[i];
    int u = t % 96, q = t / 96;

    for (int chunk = blockIdx.x; chunk < NN / 64; chunk += gridDim.x) {
        int nbase = chunk * 64;
        __syncthreads();
        for (int i = t; i < 1024; i += 768) {       // 64 nodes x 16 f4 of s
            int node = i >> 4, c4 = i & 15;
            *reinterpret_cast<float4*>(svs + node * 64 + c4 * 4) =
                reinterpret_cast<const float4*>(nf + (size_t)(nbase + node) * 160)[c4];
        }
        for (int i = t; i < 1536; i += 768) {       // 64 nodes x 24 f4 of agg_s
            int node = i / 24, c4 = i % 24;
            *reinterpret_cast<float4*>(ags + node * 96 + c4 * 4) =
                reinterpret_cast<const float4*>(g_agg + (size_t)(nbase + node) * 480)[c4];
        }
        if (t < 64) aa[t] = na[nbase + t];
        __syncthreads();

        float acc[8], ac2[8];
        #pragma unroll
        for (int k = 0; k < 8; k++) { acc[k] = 0.f; ac2[k] = 0.f; }
        #pragma unroll
        for (int c = 0; c < 64; c++) {
            float w = scws[c * 96 + u];
            #pragma unroll
            for (int k = 0; k < 8; k++) acc[k] = fmaf(svs[(q * 8 + k) * 64 + c], w, acc[k]);
        }
        #pragma unroll
        for (int c = 0; c < 96; c++) {
            float w = l2ws[c * 96 + u];
            #pragma unroll
            for (int k = 0; k < 8; k++) ac2[k] = fmaf(ags[(q * 8 + k) * 96 + c], w, ac2[k]);
        }
        #pragma unroll
        for (int k = 0; k < 8; k++) {
            int n = q * 8 + k;
            float pre = (acc[k] * INV8 + ac2[k] * (INV_SQRT96 * INV_NN)) * aa[n];
            if (u < 64) out[(size_t)(nbase + n) * 160 + u] = siluf_(pre);
            else        g_gates[(size_t)(nbase + n) * 32 + (u - 64)] = sigmoidf_(pre);
        }
    }
}

// ---------------- node post, split: vector kernel (2 CTAs/SM) ----------------
#define NPV_FLOATS 21568
#define NPV_BYTES (NPV_FLOATS * 4)
__global__ void __launch_bounds__(768, 2) np_vector_kernel(
    const float* __restrict__ nf, const float* __restrict__ na,
    const float* __restrict__ sc_wv, const float* __restrict__ lin2_wv,
    float* __restrict__ out)
{
    extern __shared__ float sm[];
    float* scwv = sm;             // 1024
    float* l2wv = sm + 1024;      // 4096
    float* svv  = sm + 5120;      // 3072 (32x96)
    float* agv  = sm + 8192;      // 12288 (32x384)
    float* gts  = sm + 20480;     // 1024 (32x32)
    float* aa   = sm + 21504;     // 32

    int t = threadIdx.x;
    for (int i = t; i < 1024; i += 768) scwv[i] = sc_wv[i];
    for (int i = t; i < 4096; i += 768) l2wv[i] = lin2_wv[i];
    int u = t % 96, q = t / 96;
    int d = u / 3, ii = u - d * 3;

    for (int chunk = blockIdx.x; chunk < NN / 32; chunk += gridDim.x) {
        int nbase = chunk * 32;
        __syncthreads();
        if (t < 768) {                              // 32 x 24 f4 of v-part (offset 64)
            int node = t / 24, c4 = t % 24;
            *reinterpret_cast<float4*>(svv + node * 96 + c4 * 4) =
                reinterpret_cast<const float4*>(nf + (size_t)(nbase + node) * 160 + 64)[c4];
        }
        for (int i = t; i < 3072; i += 768) {       // 32 x 96 f4 of agg_v (offset 96)
            int node = i / 96, c4 = i % 96;
            *reinterpret_cast<float4*>(agv + node * 384 + c4 * 4) =
                reinterpret_cast<const float4*>(g_agg + (size_t)(nbase + node) * 480 + 96)[c4];
        }
        if (t < 256) {                              // 32 x 8 f4 gates
            int node = t >> 3, c4 = t & 7;
            *reinterpret_cast<float4*>(gts + node * 32 + c4 * 4) =
                reinterpret_cast<const float4*>(g_gates + (size_t)(nbase + node) * 32)[c4];
        }
        if (t < 32) aa[t] = na[nbase + t];
        __syncthreads();

        float acc[4], ac2[4];
        #pragma unroll
        for (int k = 0; k < 4; k++) { acc[k] = 0.f; ac2[k] = 0.f; }
        #pragma unroll
        for (int c = 0; c < 32; c++) {
            float w = scwv[c * 32 + d];
            #pragma unroll
            for (int k = 0; k < 4; k++) acc[k] = fmaf(svv[(q * 4 + k) * 96 + c * 3 + ii], w, acc[k]);
        }
        #pragma unroll
        for (int c = 0; c < 128; c++) {
            float w = l2wv[c * 32 + d];
            #pragma unroll
            for (int k = 0; k < 4; k++) ac2[k] = fmaf(agv[(q * 4 + k) * 384 + c * 3 + ii], w, ac2[k]);
        }
        #pragma unroll
        for (int k = 0; k < 4; k++) {
            int n = q * 4 + k;
            float pv = (acc[k] * INV_SQRT32 + ac2[k] * (INV_SQRT128 * INV_NN)) * aa[n];
            out[(size_t)(nbase + n) * 160 + 64 + u] = gts[n * 32 + d] * pv;
        }
    }
}

// ---------------- launch ----------------
extern "C" void kernel_launch(void* const* d_in, const int* in_sizes, int n_in,
                              void* d_out, int out_size)
{
    const float* nf      = (const float*)d_in[0];
    const float* na      = (const float*)d_in[1];
    const int*   esrc    = (const int*)  d_in[2];
    const int*   edst    = (const int*)  d_in[3];
    const float* eattr   = (const float*)d_in[4];
    const float* escal   = (const float*)d_in[5];
    const float* lin1_ws = (const float*)d_in[6];
    const float* lin1_wv = (const float*)d_in[7];
    const float* fc_w1   = (const float*)d_in[8];
    const float* fc_w2   = (const float*)d_in[9];
    const float* sc_ws   = (const float*)d_in[10];
    const float* sc_wv   = (const float*)d_in[11];
    const float* lin2_ws = (const float*)d_in[12];
    const float* lin2_wv = (const float*)d_in[13];
    float* out = (float*)d_out;

    cudaFuncSetAttribute(edge_kernel,      cudaFuncAttributeMaxDynamicSharedMemorySize, ESMEM_BYTES);
    cudaFuncSetAttribute(np_scalar_kernel, cudaFuncAttributeMaxDynamicSharedMemorySize, NPS_BYTES);
    cudaFuncSetAttribute(np_vector_kernel, cudaFuncAttributeMaxDynamicSharedMemorySize, NPV_BYTES);

    zero_kernel<<<(NN * 120 + 255) / 256, 256>>>();            // idx 0
    node_pre_kernel<<<296, 640>>>(nf, na, lin1_ws, lin1_wv);   // idx 1
    dummy_kernel<<<1, 32>>>();                                 // idx 2 (steer ncu)
    edge_kernel<<<148, 1024, ESMEM_BYTES>>>(escal, esrc, edst, eattr, fc_w1, fc_w2);  // idx 3 <- profiled
    np_scalar_kernel<<<296, 768, NPS_BYTES>>>(nf, na, sc_ws, lin2_ws, out);
    np_vector_kernel<<<296, 768, NPV_BYTES>>>(nf, na, sc_wv, lin2_wv, out);
}